// round 2
// baseline (speedup 1.0000x reference)
#include <cuda_runtime.h>
#include <stdint.h>

#define NPTS 500000
#define KK 27

// Scratch (allocation-free rule: __device__ globals)
__device__ float g_h0 [NPTS * 32];   // relu(x@W00+b00)
__device__ float g_h0c[NPTS * 32];   // relu(conv3(h0,W01)+b01)
__device__ float g_h1 [NPTS * 32];   // relu(conv3(x,W10)+b10)

// ---------------------------------------------------------------------------
// 1x1 conv: [N,128] @ [128,32] + b, relu.  Warp per point, lane = cout.
// ---------------------------------------------------------------------------
__global__ __launch_bounds__(256) void k_conv1_128_32(
    const float* __restrict__ x, const float* __restrict__ W,
    const float* __restrict__ b, float* __restrict__ out)
{
    __shared__ float Ws[128 * 32];
    __shared__ float bs[32];
    const int tid = threadIdx.x;
    for (int i = tid; i < 128 * 32; i += 256) Ws[i] = W[i];
    if (tid < 32) bs[tid] = b[tid];
    __syncthreads();

    const int p = (blockIdx.x * 256 + tid) >> 5;
    const int lane = tid & 31;
    if (p >= NPTS) return;

    const float4* xr = reinterpret_cast<const float4*>(x + (size_t)p * 128);
    float acc = bs[lane];
#pragma unroll
    for (int c = 0; c < 32; c++) {
        float4 v = xr[c];  // warp-uniform broadcast load
        acc = fmaf(v.x, Ws[(4 * c + 0) * 32 + lane], acc);
        acc = fmaf(v.y, Ws[(4 * c + 1) * 32 + lane], acc);
        acc = fmaf(v.z, Ws[(4 * c + 2) * 32 + lane], acc);
        acc = fmaf(v.w, Ws[(4 * c + 3) * 32 + lane], acc);
    }
    out[(size_t)p * 32 + lane] = fmaxf(acc, 0.f);
}

// ---------------------------------------------------------------------------
// 3x3x3 gather conv: Cout=32.  Warp per point, lane = cout.
// Block-level k loop: W[k] (CIN x 32) staged in smem once per block per k.
// ---------------------------------------------------------------------------
template <int CIN, bool RELU>
__global__ __launch_bounds__(256) void k_conv3_c32(
    const float* __restrict__ f, const int* __restrict__ nbr,
    const int* __restrict__ mask, const float* __restrict__ W,
    const float* __restrict__ b, float* __restrict__ out)
{
    __shared__ float Ws[CIN * 32];
    __shared__ float bs[32];
    const int tid = threadIdx.x;
    if (tid < 32) bs[tid] = b[tid];
    const int p = (blockIdx.x * 256 + tid) >> 5;
    const int lane = tid & 31;
    const bool valid = (p < NPTS);

    float acc = 0.f;
    for (int k = 0; k < KK; k++) {
        __syncthreads();
        for (int i = tid; i < CIN * 32; i += 256) Ws[i] = W[k * CIN * 32 + i];
        __syncthreads();
        if (valid && mask[(size_t)p * KK + k] != 0) {
            const int idx = nbr[(size_t)p * KK + k];
            const float4* fr = reinterpret_cast<const float4*>(f + (size_t)idx * CIN);
#pragma unroll
            for (int c = 0; c < CIN / 4; c++) {
                float4 v = fr[c];
                acc = fmaf(v.x, Ws[(4 * c + 0) * 32 + lane], acc);
                acc = fmaf(v.y, Ws[(4 * c + 1) * 32 + lane], acc);
                acc = fmaf(v.z, Ws[(4 * c + 2) * 32 + lane], acc);
                acc = fmaf(v.w, Ws[(4 * c + 3) * 32 + lane], acc);
            }
        }
    }
    if (valid) {
        acc += bs[lane];
        if (RELU) acc = fmaxf(acc, 0.f);
        out[(size_t)p * 32 + lane] = acc;
    }
}

// ---------------------------------------------------------------------------
// 3x3x3 gather conv: Cin=32 -> Cout=64, + bias + residual(x cols 64..127),
// writes out columns [64,128).  Lane handles cout = lane and lane+32.
// ---------------------------------------------------------------------------
__global__ __launch_bounds__(256) void k_conv3_c32_o64_res(
    const float* __restrict__ f, const int* __restrict__ nbr,
    const int* __restrict__ mask, const float* __restrict__ W,
    const float* __restrict__ b, const float* __restrict__ x,
    float* __restrict__ out)
{
    __shared__ float Ws[32 * 64];
    __shared__ float bs[64];
    const int tid = threadIdx.x;
    if (tid < 64) bs[tid] = b[tid];
    const int p = (blockIdx.x * 256 + tid) >> 5;
    const int lane = tid & 31;
    const bool valid = (p < NPTS);

    float a0 = 0.f, a1 = 0.f;
    for (int k = 0; k < KK; k++) {
        __syncthreads();
        for (int i = tid; i < 32 * 64; i += 256) Ws[i] = W[k * 32 * 64 + i];
        __syncthreads();
        if (valid && mask[(size_t)p * KK + k] != 0) {
            const int idx = nbr[(size_t)p * KK + k];
            const float4* fr = reinterpret_cast<const float4*>(f + (size_t)idx * 32);
#pragma unroll
            for (int c = 0; c < 8; c++) {
                float4 v = fr[c];
                a0 = fmaf(v.x, Ws[(4 * c + 0) * 64 + lane], a0);
                a1 = fmaf(v.x, Ws[(4 * c + 0) * 64 + 32 + lane], a1);
                a0 = fmaf(v.y, Ws[(4 * c + 1) * 64 + lane], a0);
                a1 = fmaf(v.y, Ws[(4 * c + 1) * 64 + 32 + lane], a1);
                a0 = fmaf(v.z, Ws[(4 * c + 2) * 64 + lane], a0);
                a1 = fmaf(v.z, Ws[(4 * c + 2) * 64 + 32 + lane], a1);
                a0 = fmaf(v.w, Ws[(4 * c + 3) * 64 + lane], a0);
                a1 = fmaf(v.w, Ws[(4 * c + 3) * 64 + 32 + lane], a1);
            }
        }
    }
    if (valid) {
        const size_t base = (size_t)p * 128;
        out[base + 64 + lane] = a0 + bs[lane]      + x[base + 64 + lane];
        out[base + 96 + lane] = a1 + bs[32 + lane] + x[base + 96 + lane];
    }
}

// ---------------------------------------------------------------------------
// 1x1 conv: [N,32] @ [32,64] + b + residual(x cols 0..63), writes out[:,0:64).
// ---------------------------------------------------------------------------
__global__ __launch_bounds__(256) void k_conv1_32_64_res(
    const float* __restrict__ h, const float* __restrict__ W,
    const float* __restrict__ b, const float* __restrict__ x,
    float* __restrict__ out)
{
    __shared__ float Ws[32 * 64];
    __shared__ float bs[64];
    const int tid = threadIdx.x;
    for (int i = tid; i < 32 * 64; i += 256) Ws[i] = W[i];
    if (tid < 64) bs[tid] = b[tid];
    __syncthreads();

    const int p = (blockIdx.x * 256 + tid) >> 5;
    const int lane = tid & 31;
    if (p >= NPTS) return;

    const float4* hr = reinterpret_cast<const float4*>(h + (size_t)p * 32);
    float a0 = bs[lane], a1 = bs[32 + lane];
#pragma unroll
    for (int c = 0; c < 8; c++) {
        float4 v = hr[c];
        a0 = fmaf(v.x, Ws[(4 * c + 0) * 64 + lane], a0);
        a1 = fmaf(v.x, Ws[(4 * c + 0) * 64 + 32 + lane], a1);
        a0 = fmaf(v.y, Ws[(4 * c + 1) * 64 + lane], a0);
        a1 = fmaf(v.y, Ws[(4 * c + 1) * 64 + 32 + lane], a1);
        a0 = fmaf(v.z, Ws[(4 * c + 2) * 64 + lane], a0);
        a1 = fmaf(v.z, Ws[(4 * c + 2) * 64 + 32 + lane], a1);
        a0 = fmaf(v.w, Ws[(4 * c + 3) * 64 + lane], a0);
        a1 = fmaf(v.w, Ws[(4 * c + 3) * 64 + 32 + lane], a1);
    }
    const size_t base = (size_t)p * 128;
    out[base + lane]      = a0 + x[base + lane];
    out[base + 32 + lane] = a1 + x[base + 32 + lane];
}

// ---------------------------------------------------------------------------
extern "C" void kernel_launch(void* const* d_in, const int* in_sizes, int n_in,
                              void* d_out, int out_size)
{
    const float* x    = (const float*)d_in[0];
    const int*   nbr  = (const int*)  d_in[1];
    const int*   mask = (const int*)  d_in[2];   // bool -> int32 in harness
    const float* W00  = (const float*)d_in[3];
    const float* b00  = (const float*)d_in[4];
    const float* W01  = (const float*)d_in[5];
    const float* b01  = (const float*)d_in[6];
    const float* W02  = (const float*)d_in[7];
    const float* b02  = (const float*)d_in[8];
    const float* W10  = (const float*)d_in[9];
    const float* b10  = (const float*)d_in[10];
    const float* W11  = (const float*)d_in[11];
    const float* b11  = (const float*)d_in[12];
    float* out = (float*)d_out;

    float *h0, *h0c, *h1;
    cudaGetSymbolAddress((void**)&h0,  g_h0);
    cudaGetSymbolAddress((void**)&h0c, g_h0c);
    cudaGetSymbolAddress((void**)&h1,  g_h1);

    const int blocks = (NPTS + 7) / 8;  // 8 warps (points) per 256-thread block

    // branch 0: 1x1 -> relu
    k_conv1_128_32<<<blocks, 256>>>(x, W00, b00, h0);
    // branch 1: 3x3 -> relu
    k_conv3_c32<128, true><<<blocks, 256>>>(x, nbr, mask, W10, b10, h1);
    // branch 0: 3x3 -> relu
    k_conv3_c32<32, true><<<blocks, 256>>>(h0, nbr, mask, W01, b01, h0c);
    // branch 0 tail: 1x1 + bias + residual -> out[:, 0:64)
    k_conv1_32_64_res<<<blocks, 256>>>(h0c, W02, b02, x, out);
    // branch 1 tail: 3x3 + bias + residual -> out[:, 64:128)
    k_conv3_c32_o64_res<<<blocks, 256>>>(h1, nbr, mask, W11, b11, x, out);
}

// round 4
// speedup vs baseline: 2.8800x; 2.8800x over previous
#include <cuda_runtime.h>
#include <stdint.h>

#define NPTS 500000
#define KK 27

// Scratch (allocation-free rule: __device__ globals)
__device__ float g_h0 [NPTS * 32];   // relu(x@W00+b00)
__device__ float g_h0c[NPTS * 32];   // relu(conv3(h0,W01)+b01)
__device__ float g_h1 [NPTS * 32];   // relu(conv3(x,W10)+b10)

// ---------------------------------------------------------------------------
// helpers
// ---------------------------------------------------------------------------
__device__ __forceinline__ uint32_t f2tf32(float v) {
    uint32_t r;
    asm("cvt.rna.tf32.f32 %0, %1;" : "=r"(r) : "f"(v));
    return r;
}

__device__ __forceinline__ void mma_16n8k8(float* c, uint32_t a0, uint32_t a1,
                                           uint32_t a2, uint32_t a3,
                                           uint32_t b0, uint32_t b1) {
    asm volatile(
        "mma.sync.aligned.m16n8k8.row.col.f32.tf32.tf32.f32 "
        "{%0,%1,%2,%3}, {%4,%5,%6,%7}, {%8,%9}, {%0,%1,%2,%3};"
        : "+f"(c[0]), "+f"(c[1]), "+f"(c[2]), "+f"(c[3])
        : "r"(a0), "r"(a1), "r"(a2), "r"(a3), "r"(b0), "r"(b1));
}

// ---------------------------------------------------------------------------
// 3x3x3 gather conv via mma.sync (tf32).
// Block: 256 threads = 8 warps; each warp owns 16 points (M=16, N=COUT).
// Block tile: 128 points. Per k: stage W[k] (CIN x COUT, tf32) in smem, then
// dense warp-tile GEMM with per-row gathered/zero-filled A fragments.
// MODE 0: out[N,COUT] = relu(conv + b)
// MODE 1: out[N,128] cols [64,128) = conv + b + x[:,64:128)   (COUT=64)
// ---------------------------------------------------------------------------
template <int CIN, int COUT, int MODE>
__global__ __launch_bounds__(256) void k_conv3_mma(
    const float* __restrict__ f, const int* __restrict__ nbr,
    const int* __restrict__ mask, const float* __restrict__ W,
    const float* __restrict__ b, const float* __restrict__ x,
    float* __restrict__ out)
{
    __shared__ int      midx[128 * KK];      // masked neighbor idx (or -1)
    __shared__ uint32_t Bs[CIN * COUT];      // W[k] as tf32 bits
    __shared__ float    bs[COUT];

    const int tid  = threadIdx.x;
    const int warp = tid >> 5;
    const int lane = tid & 31;
    const int grp  = lane >> 2;   // 0..7
    const int four = lane & 3;    // 0..3

    if (tid < COUT) bs[tid] = b[tid];

    const int pbase = blockIdx.x * 128;
    // preload (nbr,mask) slab -> midx
    for (int i = tid; i < 128 * KK; i += 256) {
        const int p = pbase + i / KK;
        int v = -1;
        if (p < NPTS) {
            const size_t g = (size_t)p * KK + (i % KK);
            if (mask[g] != 0) v = nbr[g];
        }
        midx[i] = v;
    }

    const int lr0 = warp * 16 + grp;     // local rows this lane covers
    const int lr1 = lr0 + 8;

    float acc[COUT / 8][4];
#pragma unroll
    for (int nt = 0; nt < COUT / 8; nt++)
#pragma unroll
        for (int j = 0; j < 4; j++) acc[nt][j] = 0.f;

    for (int k = 0; k < KK; k++) {
        __syncthreads();
        // stage W[k] (CIN x COUT) as tf32
        for (int i = tid; i < CIN * COUT; i += 256)
            Bs[i] = f2tf32(W[(size_t)k * CIN * COUT + i]);
        __syncthreads();

        const int i0 = midx[lr0 * KK + k];
        const int i1 = midx[lr1 * KK + k];
        const float* r0 = f + (size_t)(i0 < 0 ? 0 : i0) * CIN;
        const float* r1 = f + (size_t)(i1 < 0 ? 0 : i1) * CIN;

#pragma unroll
        for (int c = 0; c < CIN; c += 8) {
            uint32_t a0 = 0, a1 = 0, a2 = 0, a3 = 0;
            if (i0 >= 0) {
                a0 = f2tf32(__ldg(r0 + c + four));
                a2 = f2tf32(__ldg(r0 + c + four + 4));
            }
            if (i1 >= 0) {
                a1 = f2tf32(__ldg(r1 + c + four));
                a3 = f2tf32(__ldg(r1 + c + four + 4));
            }
#pragma unroll
            for (int nt = 0; nt < COUT / 8; nt++) {
                const uint32_t b0 = Bs[(c + four) * COUT + nt * 8 + grp];
                const uint32_t b1 = Bs[(c + four + 4) * COUT + nt * 8 + grp];
                mma_16n8k8(acc[nt], a0, a1, a2, a3, b0, b1);
            }
        }
    }

    // epilogue
    const int p0 = pbase + lr0;
    const int p1 = pbase + lr1;
#pragma unroll
    for (int nt = 0; nt < COUT / 8; nt++) {
        const int col = nt * 8 + 2 * four;
        if (MODE == 0) {
            if (p0 < NPTS) {
                float2 v = {fmaxf(acc[nt][0] + bs[col], 0.f),
                            fmaxf(acc[nt][1] + bs[col + 1], 0.f)};
                *reinterpret_cast<float2*>(out + (size_t)p0 * COUT + col) = v;
            }
            if (p1 < NPTS) {
                float2 v = {fmaxf(acc[nt][2] + bs[col], 0.f),
                            fmaxf(acc[nt][3] + bs[col + 1], 0.f)};
                *reinterpret_cast<float2*>(out + (size_t)p1 * COUT + col) = v;
            }
        } else {
            const int oc = 64 + col;
            if (p0 < NPTS) {
                const size_t a = (size_t)p0 * 128 + oc;
                float2 xr = *reinterpret_cast<const float2*>(x + a);
                float2 v = {acc[nt][0] + bs[col] + xr.x,
                            acc[nt][1] + bs[col + 1] + xr.y};
                *reinterpret_cast<float2*>(out + a) = v;
            }
            if (p1 < NPTS) {
                const size_t a = (size_t)p1 * 128 + oc;
                float2 xr = *reinterpret_cast<const float2*>(x + a);
                float2 v = {acc[nt][2] + bs[col] + xr.x,
                            acc[nt][3] + bs[col + 1] + xr.y};
                *reinterpret_cast<float2*>(out + a) = v;
            }
        }
    }
}

// ---------------------------------------------------------------------------
// 1x1 conv: [N,128] @ [128,32] + b, relu.  Warp per point, lane = cout.
// ---------------------------------------------------------------------------
__global__ __launch_bounds__(256) void k_conv1_128_32(
    const float* __restrict__ x, const float* __restrict__ W,
    const float* __restrict__ b, float* __restrict__ out)
{
    __shared__ float Ws[128 * 32];
    __shared__ float bs[32];
    const int tid = threadIdx.x;
    for (int i = tid; i < 128 * 32; i += 256) Ws[i] = W[i];
    if (tid < 32) bs[tid] = b[tid];
    __syncthreads();

    const int p = (blockIdx.x * 256 + tid) >> 5;
    const int lane = tid & 31;
    if (p >= NPTS) return;

    const float4* xr = reinterpret_cast<const float4*>(x + (size_t)p * 128);
    float acc = bs[lane];
#pragma unroll
    for (int c = 0; c < 32; c++) {
        float4 v = xr[c];
        acc = fmaf(v.x, Ws[(4 * c + 0) * 32 + lane], acc);
        acc = fmaf(v.y, Ws[(4 * c + 1) * 32 + lane], acc);
        acc = fmaf(v.z, Ws[(4 * c + 2) * 32 + lane], acc);
        acc = fmaf(v.w, Ws[(4 * c + 3) * 32 + lane], acc);
    }
    out[(size_t)p * 32 + lane] = fmaxf(acc, 0.f);
}

// ---------------------------------------------------------------------------
// 1x1 conv: [N,32] @ [32,64] + b + residual(x cols 0..63), writes out[:,0:64).
// ---------------------------------------------------------------------------
__global__ __launch_bounds__(256) void k_conv1_32_64_res(
    const float* __restrict__ h, const float* __restrict__ W,
    const float* __restrict__ b, const float* __restrict__ x,
    float* __restrict__ out)
{
    __shared__ float Ws[32 * 64];
    __shared__ float bs[64];
    const int tid = threadIdx.x;
    for (int i = tid; i < 32 * 64; i += 256) Ws[i] = W[i];
    if (tid < 64) bs[tid] = b[tid];
    __syncthreads();

    const int p = (blockIdx.x * 256 + tid) >> 5;
    const int lane = tid & 31;
    if (p >= NPTS) return;

    const float4* hr = reinterpret_cast<const float4*>(h + (size_t)p * 32);
    float a0 = bs[lane], a1 = bs[32 + lane];
#pragma unroll
    for (int c = 0; c < 8; c++) {
        float4 v = hr[c];
        a0 = fmaf(v.x, Ws[(4 * c + 0) * 64 + lane], a0);
        a1 = fmaf(v.x, Ws[(4 * c + 0) * 64 + 32 + lane], a1);
        a0 = fmaf(v.y, Ws[(4 * c + 1) * 64 + lane], a0);
        a1 = fmaf(v.y, Ws[(4 * c + 1) * 64 + 32 + lane], a1);
        a0 = fmaf(v.z, Ws[(4 * c + 2) * 64 + lane], a0);
        a1 = fmaf(v.z, Ws[(4 * c + 2) * 64 + 32 + lane], a1);
        a0 = fmaf(v.w, Ws[(4 * c + 3) * 64 + lane], a0);
        a1 = fmaf(v.w, Ws[(4 * c + 3) * 64 + 32 + lane], a1);
    }
    const size_t base = (size_t)p * 128;
    out[base + lane]      = a0 + x[base + lane];
    out[base + 32 + lane] = a1 + x[base + 32 + lane];
}

// ---------------------------------------------------------------------------
extern "C" void kernel_launch(void* const* d_in, const int* in_sizes, int n_in,
                              void* d_out, int out_size)
{
    const float* x    = (const float*)d_in[0];
    const int*   nbr  = (const int*)  d_in[1];
    const int*   mask = (const int*)  d_in[2];   // bool -> int32 in harness
    const float* W00  = (const float*)d_in[3];
    const float* b00  = (const float*)d_in[4];
    const float* W01  = (const float*)d_in[5];
    const float* b01  = (const float*)d_in[6];
    const float* W02  = (const float*)d_in[7];
    const float* b02  = (const float*)d_in[8];
    const float* W10  = (const float*)d_in[9];
    const float* b10  = (const float*)d_in[10];
    const float* W11  = (const float*)d_in[11];
    const float* b11  = (const float*)d_in[12];
    float* out = (float*)d_out;

    float *h0, *h0c, *h1;
    cudaGetSymbolAddress((void**)&h0,  g_h0);
    cudaGetSymbolAddress((void**)&h0c, g_h0c);
    cudaGetSymbolAddress((void**)&h1,  g_h1);

    const int blocks1 = (NPTS + 7) / 8;      // warp-per-point kernels
    const int blocks3 = (NPTS + 127) / 128;  // mma conv3: 128 points/block

    // branch 0: 1x1 -> relu
    k_conv1_128_32<<<blocks1, 256>>>(x, W00, b00, h0);
    // branch 1: 3x3 -> relu
    k_conv3_mma<128, 32, 0><<<blocks3, 256>>>(x, nbr, mask, W10, b10, nullptr, h1);
    // branch 0: 3x3 -> relu
    k_conv3_mma<32, 32, 0><<<blocks3, 256>>>(h0, nbr, mask, W01, b01, nullptr, h0c);
    // branch 0 tail: 1x1 + bias + residual -> out[:, 0:64)
    k_conv1_32_64_res<<<blocks1, 256>>>(h0c, W02, b02, x, out);
    // branch 1 tail: 3x3 + bias + residual -> out[:, 64:128)
    k_conv3_mma<32, 64, 1><<<blocks3, 256>>>(h1, nbr, mask, W11, b11, x, out);
}

// round 5
// speedup vs baseline: 4.3794x; 1.5206x over previous
#include <cuda_runtime.h>
#include <stdint.h>

#define NPTS 500000
#define KK 27

// Scratch (allocation-free rule: __device__ globals)
__device__ float g_h0 [NPTS * 32];
__device__ float g_h0c[NPTS * 32];
__device__ float g_h1 [NPTS * 32];

// Permuted tf32 weights, fragment-ordered:
//   slot s = ((k*PAIRS + pr)*NTS + nt)*32 + lane, each slot = uint4
//   {B[pr*16+four][col], B[pr*16+four+4][col], B[pr*16+8+four][col], B[pr*16+12+four][col]}
//   with four=lane&3, grp=lane>>2, col=nt*8+grp.
// Sizes (uint4): W10: 27*8*4*32=27648, W01: 27*2*4*32=6912, W11: 27*2*8*32=13824
#define WP10_OFF 0
#define WP01_OFF 27648
#define WP11_OFF (27648 + 6912)
__device__ uint4 g_wperm[27648 + 6912 + 13824];

// ---------------------------------------------------------------------------
__device__ __forceinline__ uint32_t f2tf32(float v) {
    uint32_t r;
    asm("cvt.rna.tf32.f32 %0, %1;" : "=r"(r) : "f"(v));
    return r;
}

__device__ __forceinline__ void mma_16n8k8(float* c, uint32_t a0, uint32_t a1,
                                           uint32_t a2, uint32_t a3,
                                           uint32_t b0, uint32_t b1) {
    asm volatile(
        "mma.sync.aligned.m16n8k8.row.col.f32.tf32.tf32.f32 "
        "{%0,%1,%2,%3}, {%4,%5,%6,%7}, {%8,%9}, {%0,%1,%2,%3};"
        : "+f"(c[0]), "+f"(c[1]), "+f"(c[2]), "+f"(c[3])
        : "r"(a0), "r"(a1), "r"(a2), "r"(a3), "r"(b0), "r"(b1));
}

// ---------------------------------------------------------------------------
// Weight permutation prep: W [KK][CIN][COUT] f32 -> fragment-ordered tf32 uint4
// ---------------------------------------------------------------------------
template <int CIN, int COUT>
__global__ void k_permW(const float* __restrict__ W, uint4* __restrict__ dst)
{
    const int PAIRS = CIN / 16, NTS = COUT / 8;
    const int total = KK * PAIRS * NTS * 32;
    const int s = blockIdx.x * 256 + threadIdx.x;
    if (s >= total) return;
    const int lane = s & 31;
    int t = s >> 5;
    const int nt = t % NTS; t /= NTS;
    const int pr = t % PAIRS; t /= PAIRS;
    const int k = t;
    const int four = lane & 3, grp = lane >> 2;
    const int col = nt * 8 + grp;
    const int r0 = pr * 16 + four;
    const size_t base = (size_t)k * CIN * COUT + col;
    uint4 v;
    v.x = f2tf32(W[base + (size_t)(r0)      * COUT]);
    v.y = f2tf32(W[base + (size_t)(r0 + 4)  * COUT]);
    v.z = f2tf32(W[base + (size_t)(r0 + 8)  * COUT]);
    v.w = f2tf32(W[base + (size_t)(r0 + 12) * COUT]);
    dst[s] = v;
}

// ---------------------------------------------------------------------------
// 3x3x3 gather conv via mma.sync tf32, fragment-ordered weights.
// Block: 256 threads = 8 warps; 256 points per block; each warp owns 32 points
// (two m16 tiles: rows warp*32+grp+{0,8} and +{16,24}).
// MODE 0: out[N,COUT] = relu(conv+b)
// MODE 1: out[N,128] cols [64,128) = conv + b + x[:,64:128)  (COUT=64)
// ---------------------------------------------------------------------------
template <int CIN, int COUT, int MODE>
__global__ __launch_bounds__(256) void k_conv3_mma(
    const float* __restrict__ f, const int* __restrict__ nbr,
    const int* __restrict__ mask, const uint4* __restrict__ Wp,
    const float* __restrict__ b, const float* __restrict__ x,
    float* __restrict__ out)
{
    const int PAIRS = CIN / 16, NTS = COUT / 8;
    __shared__ int   midx[256 * KK];
    __shared__ uint4 Bs4[CIN * COUT / 4];
    __shared__ float bs[COUT];

    const int tid  = threadIdx.x;
    const int warp = tid >> 5;
    const int lane = tid & 31;
    const int grp  = lane >> 2;
    const int four = lane & 3;

    if (tid < COUT) bs[tid] = b[tid];

    const int pbase = blockIdx.x * 256;
    for (int i = tid; i < 256 * KK; i += 256) {
        const int p = pbase + i / KK;
        int v = -1;
        if (p < NPTS) {
            const size_t g = (size_t)p * KK + (i % KK);
            if (mask[g] != 0) v = nbr[g];
        }
        midx[i] = v;
    }

    // 4 rows per lane: local rows lr+{0,8,16,24}
    const int lr = warp * 32 + grp;

    float acc0[NTS][4], acc1[NTS][4];
#pragma unroll
    for (int nt = 0; nt < NTS; nt++)
#pragma unroll
        for (int j = 0; j < 4; j++) { acc0[nt][j] = 0.f; acc1[nt][j] = 0.f; }

    const int slabN = PAIRS * NTS * 32;   // uint4 per k

    for (int k = 0; k < KK; k++) {
        __syncthreads();
        for (int i = tid; i < slabN; i += 256)
            Bs4[i] = Wp[(size_t)k * slabN + i];
        __syncthreads();

        int idx[4];
#pragma unroll
        for (int r = 0; r < 4; r++) idx[r] = midx[(lr + r * 8) * KK + k];
        const float* rows[4];
#pragma unroll
        for (int r = 0; r < 4; r++)
            rows[r] = f + (size_t)(idx[r] < 0 ? 0 : idx[r]) * CIN;

#pragma unroll
        for (int pr = 0; pr < PAIRS; pr++) {
            uint32_t A[4][4];   // [row][elem: four, four+4, four+8, four+12]
#pragma unroll
            for (int r = 0; r < 4; r++) {
                if (idx[r] >= 0) {
                    const float* rp = rows[r] + pr * 16 + four;
                    A[r][0] = f2tf32(rp[0]);
                    A[r][1] = f2tf32(rp[4]);
                    A[r][2] = f2tf32(rp[8]);
                    A[r][3] = f2tf32(rp[12]);
                } else {
                    A[r][0] = A[r][1] = A[r][2] = A[r][3] = 0u;
                }
            }
#pragma unroll
            for (int nt = 0; nt < NTS; nt++) {
                const uint4 B = Bs4[(pr * NTS + nt) * 32 + lane];
                // m-tile 0 (rows 0,1): even chunk then odd chunk
                mma_16n8k8(acc0[nt], A[0][0], A[1][0], A[0][1], A[1][1], B.x, B.y);
                mma_16n8k8(acc0[nt], A[0][2], A[1][2], A[0][3], A[1][3], B.z, B.w);
                // m-tile 1 (rows 2,3)
                mma_16n8k8(acc1[nt], A[2][0], A[3][0], A[2][1], A[3][1], B.x, B.y);
                mma_16n8k8(acc1[nt], A[2][2], A[3][2], A[2][3], A[3][3], B.z, B.w);
            }
        }
    }

    // epilogue: m-tile t, acc[ nt ][0..1] -> row lr+32t? mapping:
    // acc0: rows lr (c0,c1 = acc[0],acc[1]) and lr+8 (acc[2],acc[3])
    // acc1: rows lr+16 and lr+24
#pragma unroll
    for (int t = 0; t < 2; t++) {
#pragma unroll
        for (int half = 0; half < 2; half++) {
            const int p = pbase + lr + t * 16 + half * 8;
            if (p >= NPTS) continue;
#pragma unroll
            for (int nt = 0; nt < NTS; nt++) {
                const float c0 = (t == 0) ? acc0[nt][half * 2]     : acc1[nt][half * 2];
                const float c1 = (t == 0) ? acc0[nt][half * 2 + 1] : acc1[nt][half * 2 + 1];
                const int col = nt * 8 + 2 * four;
                if (MODE == 0) {
                    float2 v = {fmaxf(c0 + bs[col], 0.f), fmaxf(c1 + bs[col + 1], 0.f)};
                    *reinterpret_cast<float2*>(out + (size_t)p * COUT + col) = v;
                } else {
                    const size_t a = (size_t)p * 128 + 64 + col;
                    float2 xr = *reinterpret_cast<const float2*>(x + a);
                    float2 v = {c0 + bs[col] + xr.x, c1 + bs[col + 1] + xr.y};
                    *reinterpret_cast<float2*>(out + a) = v;
                }
            }
        }
    }
}

// ---------------------------------------------------------------------------
// 1x1 conv: [N,128] @ [128,32] + b, relu.  Warp per point, lane = cout.
// ---------------------------------------------------------------------------
__global__ __launch_bounds__(256) void k_conv1_128_32(
    const float* __restrict__ x, const float* __restrict__ W,
    const float* __restrict__ b, float* __restrict__ out)
{
    __shared__ float Ws[128 * 32];
    __shared__ float bs[32];
    const int tid = threadIdx.x;
    for (int i = tid; i < 128 * 32; i += 256) Ws[i] = W[i];
    if (tid < 32) bs[tid] = b[tid];
    __syncthreads();

    const int p = (blockIdx.x * 256 + tid) >> 5;
    const int lane = tid & 31;
    if (p >= NPTS) return;

    const float4* xr = reinterpret_cast<const float4*>(x + (size_t)p * 128);
    float acc = bs[lane];
#pragma unroll
    for (int c = 0; c < 32; c++) {
        float4 v = xr[c];
        acc = fmaf(v.x, Ws[(4 * c + 0) * 32 + lane], acc);
        acc = fmaf(v.y, Ws[(4 * c + 1) * 32 + lane], acc);
        acc = fmaf(v.z, Ws[(4 * c + 2) * 32 + lane], acc);
        acc = fmaf(v.w, Ws[(4 * c + 3) * 32 + lane], acc);
    }
    out[(size_t)p * 32 + lane] = fmaxf(acc, 0.f);
}

// ---------------------------------------------------------------------------
// 1x1 conv: [N,32] @ [32,64] + b + residual(x cols 0..63), writes out[:,0:64).
// ---------------------------------------------------------------------------
__global__ __launch_bounds__(256) void k_conv1_32_64_res(
    const float* __restrict__ h, const float* __restrict__ W,
    const float* __restrict__ b, const float* __restrict__ x,
    float* __restrict__ out)
{
    __shared__ float Ws[32 * 64];
    __shared__ float bs[64];
    const int tid = threadIdx.x;
    for (int i = tid; i < 32 * 64; i += 256) Ws[i] = W[i];
    if (tid < 64) bs[tid] = b[tid];
    __syncthreads();

    const int p = (blockIdx.x * 256 + tid) >> 5;
    const int lane = tid & 31;
    if (p >= NPTS) return;

    const float4* hr = reinterpret_cast<const float4*>(h + (size_t)p * 32);
    float a0 = bs[lane], a1 = bs[32 + lane];
#pragma unroll
    for (int c = 0; c < 8; c++) {
        float4 v = hr[c];
        a0 = fmaf(v.x, Ws[(4 * c + 0) * 64 + lane], a0);
        a1 = fmaf(v.x, Ws[(4 * c + 0) * 64 + 32 + lane], a1);
        a0 = fmaf(v.y, Ws[(4 * c + 1) * 64 + lane], a0);
        a1 = fmaf(v.y, Ws[(4 * c + 1) * 64 + 32 + lane], a1);
        a0 = fmaf(v.z, Ws[(4 * c + 2) * 64 + lane], a0);
        a1 = fmaf(v.z, Ws[(4 * c + 2) * 64 + 32 + lane], a1);
        a0 = fmaf(v.w, Ws[(4 * c + 3) * 64 + lane], a0);
        a1 = fmaf(v.w, Ws[(4 * c + 3) * 64 + 32 + lane], a1);
    }
    const size_t base = (size_t)p * 128;
    out[base + lane]      = a0 + x[base + lane];
    out[base + 32 + lane] = a1 + x[base + 32 + lane];
}

// ---------------------------------------------------------------------------
extern "C" void kernel_launch(void* const* d_in, const int* in_sizes, int n_in,
                              void* d_out, int out_size)
{
    const float* x    = (const float*)d_in[0];
    const int*   nbr  = (const int*)  d_in[1];
    const int*   mask = (const int*)  d_in[2];   // bool -> int32 in harness
    const float* W00  = (const float*)d_in[3];
    const float* b00  = (const float*)d_in[4];
    const float* W01  = (const float*)d_in[5];
    const float* b01  = (const float*)d_in[6];
    const float* W02  = (const float*)d_in[7];
    const float* b02  = (const float*)d_in[8];
    const float* W10  = (const float*)d_in[9];
    const float* b10  = (const float*)d_in[10];
    const float* W11  = (const float*)d_in[11];
    const float* b11  = (const float*)d_in[12];
    float* out = (float*)d_out;

    float *h0, *h0c, *h1;
    uint4* wp;
    cudaGetSymbolAddress((void**)&h0,  g_h0);
    cudaGetSymbolAddress((void**)&h0c, g_h0c);
    cudaGetSymbolAddress((void**)&h1,  g_h1);
    cudaGetSymbolAddress((void**)&wp,  g_wperm);

    // weight permutation (tiny)
    k_permW<128, 32><<<(27648 + 255) / 256, 256>>>(W10, wp + WP10_OFF);
    k_permW< 32, 32><<<( 6912 + 255) / 256, 256>>>(W01, wp + WP01_OFF);
    k_permW< 32, 64><<<(13824 + 255) / 256, 256>>>(W11, wp + WP11_OFF);

    const int blocks1 = (NPTS + 7) / 8;
    const int blocks3 = (NPTS + 255) / 256;

    // branch 0: 1x1 -> relu
    k_conv1_128_32<<<blocks1, 256>>>(x, W00, b00, h0);
    // branch 1: 3x3 -> relu
    k_conv3_mma<128, 32, 0><<<blocks3, 256>>>(x, nbr, mask, wp + WP10_OFF, b10, nullptr, h1);
    // branch 0: 3x3 -> relu
    k_conv3_mma<32, 32, 0><<<blocks3, 256>>>(h0, nbr, mask, wp + WP01_OFF, b01, nullptr, h0c);
    // branch 0 tail: 1x1 + bias + residual -> out[:, 0:64)
    k_conv1_32_64_res<<<blocks1, 256>>>(h0c, W02, b02, x, out);
    // branch 1 tail: 3x3 + bias + residual -> out[:, 64:128)
    k_conv3_mma<32, 64, 1><<<blocks3, 256>>>(h1, nbr, mask, wp + WP11_OFF, b11, x, out);
}